// round 8
// baseline (speedup 1.0000x reference)
#include <cuda_runtime.h>
#include <cuda_bf16.h>

// Problem constants
#define SEQ_LEN 512
#define EMBED_DIM 768
#define MAX_SPAN_LEN 16
#define WIDTH_EMB 50
#define NUM_LABELS 9
#define N_SPANS 32768
#define W_COLS (3 * EMBED_DIM + WIDTH_EMB)   // 2354

// Padded row stride so each 9-float table row is 48B (16B aligned) -> float4 loads
#define PSTRIDE 12

// Scratch tables (device globals; no allocation allowed)
__device__ float g_ps[SEQ_LEN * PSTRIDE];        // W[:,0:768]    . seq[t]
__device__ float g_pe[SEQ_LEN * PSTRIDE];        // W[:,768:1536] . seq[t]
__device__ float g_pa[SEQ_LEN * PSTRIDE];        // W[:,1536:2304]. seq[t]   (pre-scan)
__device__ float g_pacs[(SEQ_LEN + 8) * PSTRIDE];// exclusive scan of g_pa over t (513 rows used)
__device__ float g_pw[(MAX_SPAN_LEN + 1) * PSTRIDE]; // W[:,2304:] . width_table[w] + b
__device__ float g_invw[MAX_SPAN_LEN + 1];

// ---------------------------------------------------------------------------
// Kernel A: per-token projections.
// Each block: 8 tokens (4 warps x 2 tokens) x 14 of the 27 outputs.
// grid = 64 token-groups x 2 output-halves. Halves overlap at output 13
// (both compute the identical full dot product -> benign duplicate store).
//   - single smem fill (42 KB), single barrier
//   - seq prefetched into regs BEFORE the fill so LDG latency hides under it
//   - inner loop: pure LDS.64 + FMA, 28 independent accumulator chains
//   - all W offsets compile-time via OBASE template
// ---------------------------------------------------------------------------
#define PROJ_TPB 128
#define NOUT 14
#define K2 (EMBED_DIM / 2)          // 384 float2 per output row

template <int OBASE>
__device__ __forceinline__ void proj_body(const float* __restrict__ seq,
                                          const float* __restrict__ W,
                                          float2* __restrict__ ws,
                                          int tg) {
    const int warp = threadIdx.x >> 5;
    const int lane = threadIdx.x & 31;
    const int t0 = tg * 8 + warp * 2;

    const float2* __restrict__ w2 = (const float2*)W;
    const float2* __restrict__ s2a = (const float2*)(seq + (size_t)t0 * EMBED_DIM);
    const float2* __restrict__ s2b = (const float2*)(seq + (size_t)(t0 + 1) * EMBED_DIM);

    // prefetch both tokens' seq rows (24 independent coalesced LDG.64)
    float2 sv0[12], sv1[12];
    #pragma unroll
    for (int kk = 0; kk < 12; kk++) sv0[kk] = s2a[kk * 32 + lane];
    #pragma unroll
    for (int kk = 0; kk < 12; kk++) sv1[kk] = s2b[kk * 32 + lane];

    // cooperative fill: 14 output rows x 384 float2 (offsets compile-time per oo)
    #pragma unroll
    for (int i = threadIdx.x; i < NOUT * K2; i += PROJ_TPB) {
        const int oo = i / K2;
        const int j2 = i - oo * K2;
        const int o = OBASE + oo;
        const int kblk = o / 9;
        const int l = o - kblk * 9;
        ws[i] = __ldg(w2 + l * (W_COLS / 2) + kblk * (EMBED_DIM / 2) + j2);
    }
    __syncthreads();

    float acc0[NOUT], acc1[NOUT];
    #pragma unroll
    for (int o = 0; o < NOUT; o++) { acc0[o] = 0.f; acc1[o] = 0.f; }

    #pragma unroll
    for (int kk = 0; kk < 12; kk++) {
        const float2 s0 = sv0[kk];
        const float2 s1 = sv1[kk];
        #pragma unroll
        for (int oo = 0; oo < NOUT; oo++) {
            const float2 wv = ws[oo * K2 + kk * 32 + lane];
            acc0[oo] = fmaf(s0.x, wv.x, fmaf(s0.y, wv.y, acc0[oo]));
            acc1[oo] = fmaf(s1.x, wv.x, fmaf(s1.y, wv.y, acc1[oo]));
        }
    }

    // warp reductions + scatter (lane 0 writes both tokens)
    #pragma unroll
    for (int oo = 0; oo < NOUT; oo++) {
        float v0 = acc0[oo], v1 = acc1[oo];
        #pragma unroll
        for (int off = 16; off; off >>= 1) {
            v0 += __shfl_down_sync(0xffffffffu, v0, off);
            v1 += __shfl_down_sync(0xffffffffu, v1, off);
        }
        if (lane == 0) {
            const int o = OBASE + oo;
            const int kblk = o / 9;
            const int l = o - kblk * 9;
            float* tbl = (kblk == 0) ? g_ps : (kblk == 1) ? g_pe : g_pa;
            tbl[t0 * PSTRIDE + l] = v0;
            tbl[(t0 + 1) * PSTRIDE + l] = v1;
        }
    }
}

__global__ __launch_bounds__(PROJ_TPB) void proj_kernel(const float* __restrict__ seq,
                                                        const float* __restrict__ W) {
    __shared__ float2 ws[NOUT * K2];    // 42 KB
    const int bo = blockIdx.x & 1;
    const int tg = blockIdx.x >> 1;
    if (bo == 0) proj_body<0>(seq, W, ws, tg);
    else         proj_body<13>(seq, W, ws, tg);
}

// ---------------------------------------------------------------------------
// Kernel B: single block. (1) width-projection LUT + bias, (2) 1/w LUT,
// (3) exclusive prefix-scan of g_pa over tokens: warp-per-label.
// ---------------------------------------------------------------------------
__global__ __launch_bounds__(288) void scan_kernel(const float* __restrict__ width_table,
                                                   const float* __restrict__ W,
                                                   const float* __restrict__ b) {
    const int tid = threadIdx.x;

    // pw[w][l] = b[l] + width_table[w] . W[l, 2304:2354]
    if (tid < (MAX_SPAN_LEN + 1) * NUM_LABELS) {
        const int w = tid / NUM_LABELS;
        const int l = tid - w * NUM_LABELS;
        const float* wrow = W + (size_t)l * W_COLS + 3 * EMBED_DIM;
        const float* wt = width_table + w * WIDTH_EMB;
        float acc = b[l];
        #pragma unroll
        for (int j = 0; j < WIDTH_EMB; j++)
            acc = fmaf(wt[j], wrow[j], acc);
        g_pw[w * PSTRIDE + l] = acc;
    }
    if (tid <= MAX_SPAN_LEN)
        g_invw[tid] = 1.0f / (float)(tid < 1 ? 1 : tid);

    // exclusive scan over t=0..512 for each label column (9 warps)
    const int warp = tid >> 5;
    const int lane = tid & 31;
    if (warp < NUM_LABELS) {
        const int l = warp;
        float carry = 0.f;
        #pragma unroll 1
        for (int c = 0; c < 17; c++) {
            const int t = c * 32 + lane;
            const float v = (t < SEQ_LEN) ? g_pa[t * PSTRIDE + l] : 0.f;
            float x = v;
            #pragma unroll
            for (int off = 1; off < 32; off <<= 1) {
                float y = __shfl_up_sync(0xffffffffu, x, off);
                if (lane >= off) x += y;
            }
            const float excl = carry + x - v;
            if (t <= SEQ_LEN)
                g_pacs[t * PSTRIDE + l] = excl;
            carry += __shfl_sync(0xffffffffu, x, 31);
        }
    }
}

// ---------------------------------------------------------------------------
// Kernel C: one thread per span; all table rows are 3x float4; output staged
// through smem for coalesced float4 stores.
// ---------------------------------------------------------------------------
#define SPAN_BLK 256
__global__ __launch_bounds__(SPAN_BLK) void span_kernel(const int* __restrict__ sidx,
                                                        const int* __restrict__ eidx,
                                                        const int* __restrict__ widx,
                                                        float* __restrict__ out) {
    __shared__ float so[SPAN_BLK * NUM_LABELS];
    const int n = blockIdx.x * SPAN_BLK + threadIdx.x;

    const int s = sidx[n];
    const int e = eidx[n];
    const int w = widx[n];
    const float invw = g_invw[w];

    const float4* ps = (const float4*)(g_ps + s * PSTRIDE);
    const float4* pe = (const float4*)(g_pe + e * PSTRIDE);
    const float4* c0 = (const float4*)(g_pacs + s * PSTRIDE);
    const float4* c1 = (const float4*)(g_pacs + e * PSTRIDE);
    const float4* pw = (const float4*)(g_pw + w * PSTRIDE);

    float r[12];
    #pragma unroll
    for (int q = 0; q < 3; q++) {
        const float4 a = ps[q], bb = pe[q], x0 = c0[q], x1 = c1[q], d = pw[q];
        r[q * 4 + 0] = a.x + bb.x + (x1.x - x0.x) * invw + d.x;
        r[q * 4 + 1] = a.y + bb.y + (x1.y - x0.y) * invw + d.y;
        r[q * 4 + 2] = a.z + bb.z + (x1.z - x0.z) * invw + d.z;
        r[q * 4 + 3] = a.w + bb.w + (x1.w - x0.w) * invw + d.w;
    }

    #pragma unroll
    for (int l = 0; l < NUM_LABELS; l++)
        so[threadIdx.x * NUM_LABELS + l] = r[l];
    __syncthreads();

    float4* ob = (float4*)(out + (size_t)blockIdx.x * SPAN_BLK * NUM_LABELS);
    const float4* sb = (const float4*)so;
    #pragma unroll
    for (int i = threadIdx.x; i < SPAN_BLK * NUM_LABELS / 4; i += SPAN_BLK)
        ob[i] = sb[i];
}

// ---------------------------------------------------------------------------
// Launcher
// ---------------------------------------------------------------------------
extern "C" void kernel_launch(void* const* d_in, const int* in_sizes, int n_in,
                              void* d_out, int out_size) {
    const float* seq   = (const float*)d_in[0];   // [1, 512, 768]
    const int*   sidx  = (const int*)d_in[1];     // [32768]
    const int*   eidx  = (const int*)d_in[2];     // [32768]
    const int*   widx  = (const int*)d_in[3];     // [32768]
    const float* wtab  = (const float*)d_in[4];   // [17, 50]
    const float* W     = (const float*)d_in[5];   // [9, 2354]
    const float* b     = (const float*)d_in[6];   // [9]
    float* out = (float*)d_out;                   // [32768, 9]

    proj_kernel<<<128, PROJ_TPB>>>(seq, W);
    scan_kernel<<<1, 288>>>(wtab, W, b);
    span_kernel<<<N_SPANS / SPAN_BLK, SPAN_BLK>>>(sidx, eidx, widx, out);
}

// round 9
// speedup vs baseline: 1.0935x; 1.0935x over previous
#include <cuda_runtime.h>
#include <cuda_bf16.h>

// Problem constants
#define SEQ_LEN 512
#define EMBED_DIM 768
#define MAX_SPAN_LEN 16
#define WIDTH_EMB 50
#define NUM_LABELS 9
#define N_SPANS 32768
#define W_COLS (3 * EMBED_DIM + WIDTH_EMB)   // 2354

// Padded row stride so each 9-float table row is 48B (16B aligned) -> float4 loads
#define PSTRIDE 12

// Scratch tables (device globals; no allocation allowed)
__device__ float g_ps[SEQ_LEN * PSTRIDE];        // W[:,0:768]    . seq[t]
__device__ float g_pe[SEQ_LEN * PSTRIDE];        // W[:,768:1536] . seq[t]
__device__ float g_pa[SEQ_LEN * PSTRIDE];        // W[:,1536:2304]. seq[t]   (pre-scan)
__device__ float g_pacs[(SEQ_LEN + 8) * PSTRIDE];// exclusive scan of g_pa over t (513 rows used)
__device__ float g_pw[(MAX_SPAN_LEN + 1) * PSTRIDE]; // W[:,2304:] . width_table[w] + b
__device__ float g_invw[MAX_SPAN_LEN + 1];

// ---------------------------------------------------------------------------
// Kernel A: per-token projections.
// Block: 16 tokens (8 warps x 2 tokens) x 7 (or 6) of the 27 outputs.
// grid = 32 token-groups x 4 output-groups = 128 blocks (full chip),
// 8 warps/block = 2 warps/SMSP for latency hiding.
//   - smem tile 21 KB, single fill, single barrier
//   - seq prefetched into regs BEFORE the fill (LDG latency hides under fill)
//   - warp shares each wv between 2 tokens -> halves smem crossbar traffic
//   - exact output partition 7/7/7/6 via template (no duplicate writes)
// ---------------------------------------------------------------------------
#define PROJ_TPB 256
#define K2 (EMBED_DIM / 2)          // 384 float2 per output row
#define NOUT_MAX 7

template <int OBASE, int ONUM>
__device__ __forceinline__ void proj_body(const float* __restrict__ seq,
                                          const float* __restrict__ W,
                                          float2* __restrict__ ws,
                                          int tg) {
    const int warp = threadIdx.x >> 5;
    const int lane = threadIdx.x & 31;
    const int t0 = tg * 16 + warp * 2;

    const float2* __restrict__ w2 = (const float2*)W;
    const float2* __restrict__ s2a = (const float2*)(seq + (size_t)t0 * EMBED_DIM);
    const float2* __restrict__ s2b = (const float2*)(seq + (size_t)(t0 + 1) * EMBED_DIM);

    // prefetch both tokens' seq rows (24 independent coalesced LDG.64)
    float2 sv0[12], sv1[12];
    #pragma unroll
    for (int kk = 0; kk < 12; kk++) sv0[kk] = s2a[kk * 32 + lane];
    #pragma unroll
    for (int kk = 0; kk < 12; kk++) sv1[kk] = s2b[kk * 32 + lane];

    // cooperative fill: ONUM output rows x 384 float2 (W offsets compile-time)
    #pragma unroll
    for (int i = threadIdx.x; i < ONUM * K2; i += PROJ_TPB) {
        const int oo = i / K2;
        const int j2 = i - oo * K2;
        const int o = OBASE + oo;
        const int kblk = o / 9;
        const int l = o - kblk * 9;
        ws[i] = __ldg(w2 + l * (W_COLS / 2) + kblk * (EMBED_DIM / 2) + j2);
    }
    __syncthreads();

    float acc0[ONUM], acc1[ONUM];
    #pragma unroll
    for (int o = 0; o < ONUM; o++) { acc0[o] = 0.f; acc1[o] = 0.f; }

    #pragma unroll
    for (int kk = 0; kk < 12; kk++) {
        const float2 s0 = sv0[kk];
        const float2 s1 = sv1[kk];
        #pragma unroll
        for (int oo = 0; oo < ONUM; oo++) {
            const float2 wv = ws[oo * K2 + kk * 32 + lane];
            acc0[oo] = fmaf(s0.x, wv.x, fmaf(s0.y, wv.y, acc0[oo]));
            acc1[oo] = fmaf(s1.x, wv.x, fmaf(s1.y, wv.y, acc1[oo]));
        }
    }

    // warp reductions + scatter (lane 0 writes both tokens)
    #pragma unroll
    for (int oo = 0; oo < ONUM; oo++) {
        float v0 = acc0[oo], v1 = acc1[oo];
        #pragma unroll
        for (int off = 16; off; off >>= 1) {
            v0 += __shfl_down_sync(0xffffffffu, v0, off);
            v1 += __shfl_down_sync(0xffffffffu, v1, off);
        }
        if (lane == 0) {
            const int o = OBASE + oo;
            const int kblk = o / 9;
            const int l = o - kblk * 9;
            float* tbl = (kblk == 0) ? g_ps : (kblk == 1) ? g_pe : g_pa;
            tbl[t0 * PSTRIDE + l] = v0;
            tbl[(t0 + 1) * PSTRIDE + l] = v1;
        }
    }
}

__global__ __launch_bounds__(PROJ_TPB) void proj_kernel(const float* __restrict__ seq,
                                                        const float* __restrict__ W) {
    __shared__ float2 ws[NOUT_MAX * K2];    // 21 KB
    const int bo = blockIdx.x & 3;
    const int tg = blockIdx.x >> 2;
    if      (bo == 0) proj_body<0, 7>(seq, W, ws, tg);
    else if (bo == 1) proj_body<7, 7>(seq, W, ws, tg);
    else if (bo == 2) proj_body<14, 7>(seq, W, ws, tg);
    else              proj_body<21, 6>(seq, W, ws, tg);
}

// ---------------------------------------------------------------------------
// Kernel B: single block. (1) width-projection LUT + bias, (2) 1/w LUT,
// (3) exclusive prefix-scan of g_pa over tokens: warp-per-label.
// ---------------------------------------------------------------------------
__global__ __launch_bounds__(288) void scan_kernel(const float* __restrict__ width_table,
                                                   const float* __restrict__ W,
                                                   const float* __restrict__ b) {
    const int tid = threadIdx.x;

    // pw[w][l] = b[l] + width_table[w] . W[l, 2304:2354]
    if (tid < (MAX_SPAN_LEN + 1) * NUM_LABELS) {
        const int w = tid / NUM_LABELS;
        const int l = tid - w * NUM_LABELS;
        const float* wrow = W + (size_t)l * W_COLS + 3 * EMBED_DIM;
        const float* wt = width_table + w * WIDTH_EMB;
        float acc = b[l];
        #pragma unroll
        for (int j = 0; j < WIDTH_EMB; j++)
            acc = fmaf(wt[j], wrow[j], acc);
        g_pw[w * PSTRIDE + l] = acc;
    }
    if (tid <= MAX_SPAN_LEN)
        g_invw[tid] = 1.0f / (float)(tid < 1 ? 1 : tid);

    // exclusive scan over t=0..512 for each label column (9 warps)
    const int warp = tid >> 5;
    const int lane = tid & 31;
    if (warp < NUM_LABELS) {
        const int l = warp;
        float carry = 0.f;
        #pragma unroll 1
        for (int c = 0; c < 17; c++) {
            const int t = c * 32 + lane;
            const float v = (t < SEQ_LEN) ? g_pa[t * PSTRIDE + l] : 0.f;
            float x = v;
            #pragma unroll
            for (int off = 1; off < 32; off <<= 1) {
                float y = __shfl_up_sync(0xffffffffu, x, off);
                if (lane >= off) x += y;
            }
            const float excl = carry + x - v;
            if (t <= SEQ_LEN)
                g_pacs[t * PSTRIDE + l] = excl;
            carry += __shfl_sync(0xffffffffu, x, 31);
        }
    }
}

// ---------------------------------------------------------------------------
// Kernel C: one thread per span; all table rows are 3x float4; output staged
// through smem for coalesced float4 stores.
// ---------------------------------------------------------------------------
#define SPAN_BLK 256
__global__ __launch_bounds__(SPAN_BLK) void span_kernel(const int* __restrict__ sidx,
                                                        const int* __restrict__ eidx,
                                                        const int* __restrict__ widx,
                                                        float* __restrict__ out) {
    __shared__ float so[SPAN_BLK * NUM_LABELS];
    const int n = blockIdx.x * SPAN_BLK + threadIdx.x;

    const int s = sidx[n];
    const int e = eidx[n];
    const int w = widx[n];
    const float invw = g_invw[w];

    const float4* ps = (const float4*)(g_ps + s * PSTRIDE);
    const float4* pe = (const float4*)(g_pe + e * PSTRIDE);
    const float4* c0 = (const float4*)(g_pacs + s * PSTRIDE);
    const float4* c1 = (const float4*)(g_pacs + e * PSTRIDE);
    const float4* pw = (const float4*)(g_pw + w * PSTRIDE);

    float r[12];
    #pragma unroll
    for (int q = 0; q < 3; q++) {
        const float4 a = ps[q], bb = pe[q], x0 = c0[q], x1 = c1[q], d = pw[q];
        r[q * 4 + 0] = a.x + bb.x + (x1.x - x0.x) * invw + d.x;
        r[q * 4 + 1] = a.y + bb.y + (x1.y - x0.y) * invw + d.y;
        r[q * 4 + 2] = a.z + bb.z + (x1.z - x0.z) * invw + d.z;
        r[q * 4 + 3] = a.w + bb.w + (x1.w - x0.w) * invw + d.w;
    }

    #pragma unroll
    for (int l = 0; l < NUM_LABELS; l++)
        so[threadIdx.x * NUM_LABELS + l] = r[l];
    __syncthreads();

    float4* ob = (float4*)(out + (size_t)blockIdx.x * SPAN_BLK * NUM_LABELS);
    const float4* sb = (const float4*)so;
    #pragma unroll
    for (int i = threadIdx.x; i < SPAN_BLK * NUM_LABELS / 4; i += SPAN_BLK)
        ob[i] = sb[i];
}

// ---------------------------------------------------------------------------
// Launcher
// ---------------------------------------------------------------------------
extern "C" void kernel_launch(void* const* d_in, const int* in_sizes, int n_in,
                              void* d_out, int out_size) {
    const float* seq   = (const float*)d_in[0];   // [1, 512, 768]
    const int*   sidx  = (const int*)d_in[1];     // [32768]
    const int*   eidx  = (const int*)d_in[2];     // [32768]
    const int*   widx  = (const int*)d_in[3];     // [32768]
    const float* wtab  = (const float*)d_in[4];   // [17, 50]
    const float* W     = (const float*)d_in[5];   // [9, 2354]
    const float* b     = (const float*)d_in[6];   // [9]
    float* out = (float*)d_out;                   // [32768, 9]

    proj_kernel<<<128, PROJ_TPB>>>(seq, W);
    scan_kernel<<<1, 288>>>(wtab, W, b);
    span_kernel<<<N_SPANS / SPAN_BLK, SPAN_BLK>>>(sidx, eidx, widx, out);
}

// round 10
// speedup vs baseline: 1.2743x; 1.1654x over previous
#include <cuda_runtime.h>
#include <cuda_bf16.h>

// Problem constants
#define SEQ_LEN 512
#define EMBED_DIM 768
#define MAX_SPAN_LEN 16
#define WIDTH_EMB 50
#define NUM_LABELS 9
#define N_SPANS 32768
#define W_COLS (3 * EMBED_DIM + WIDTH_EMB)   // 2354

// Padded row stride so each 9-float table row is 48B (16B aligned) -> float4 loads
#define PSTRIDE 12

// Scratch tables (device globals; no allocation allowed)
__device__ float g_ps[SEQ_LEN * PSTRIDE];        // W[:,0:768]    . seq[t]
__device__ float g_pe[SEQ_LEN * PSTRIDE];        // W[:,768:1536] . seq[t]
__device__ float g_pa[SEQ_LEN * PSTRIDE];        // W[:,1536:2304]. seq[t]   (pre-scan)
__device__ float g_pacs[(SEQ_LEN + 8) * PSTRIDE];// exclusive scan of g_pa over t (513 rows used)
__device__ float g_pw[(MAX_SPAN_LEN + 1) * PSTRIDE]; // W[:,2304:] . width_table[w] + b
__device__ float g_invw[MAX_SPAN_LEN + 1];

// ---------------------------------------------------------------------------
// Kernel A: per-token projections.
// Grid (32, 9): x = token-group (16 tokens), y = output-group (3 outputs).
// Block 256 thr = 8 warps x 2 tokens. 288 blocks -> 2 blocks/SM, 16 warps/SM.
//   - smem tile 9 KB (3 W rows), single fill, single barrier
//   - seq prefetched into regs BEFORE the fill (LDG latency hides under fill)
//   - warp shares each wv between 2 tokens -> halves smem crossbar traffic
//   - all W offsets compile-time via OBASE template (9 instantiations)
// ---------------------------------------------------------------------------
#define PROJ_TPB 256
#define K2 (EMBED_DIM / 2)          // 384 float2 per output row
#define ONUM 3

template <int OBASE>
__device__ __forceinline__ void proj_body(const float* __restrict__ seq,
                                          const float* __restrict__ W,
                                          float2* __restrict__ ws,
                                          int tg) {
    const int warp = threadIdx.x >> 5;
    const int lane = threadIdx.x & 31;
    const int t0 = tg * 16 + warp * 2;

    const float2* __restrict__ w2 = (const float2*)W;
    const float2* __restrict__ s2a = (const float2*)(seq + (size_t)t0 * EMBED_DIM);
    const float2* __restrict__ s2b = (const float2*)(seq + (size_t)(t0 + 1) * EMBED_DIM);

    // prefetch both tokens' seq rows (24 independent coalesced LDG.64)
    float2 sv0[12], sv1[12];
    #pragma unroll
    for (int kk = 0; kk < 12; kk++) sv0[kk] = s2a[kk * 32 + lane];
    #pragma unroll
    for (int kk = 0; kk < 12; kk++) sv1[kk] = s2b[kk * 32 + lane];

    // cooperative fill: 3 output rows x 384 float2 (W offsets compile-time)
    #pragma unroll
    for (int i = threadIdx.x; i < ONUM * K2; i += PROJ_TPB) {
        const int oo = i / K2;
        const int j2 = i - oo * K2;
        const int o = OBASE + oo;
        const int kblk = o / 9;
        const int l = o - kblk * 9;
        ws[i] = __ldg(w2 + l * (W_COLS / 2) + kblk * (EMBED_DIM / 2) + j2);
    }
    __syncthreads();

    float acc0[ONUM], acc1[ONUM];
    #pragma unroll
    for (int o = 0; o < ONUM; o++) { acc0[o] = 0.f; acc1[o] = 0.f; }

    #pragma unroll
    for (int kk = 0; kk < 12; kk++) {
        const float2 s0 = sv0[kk];
        const float2 s1 = sv1[kk];
        #pragma unroll
        for (int oo = 0; oo < ONUM; oo++) {
            const float2 wv = ws[oo * K2 + kk * 32 + lane];
            acc0[oo] = fmaf(s0.x, wv.x, fmaf(s0.y, wv.y, acc0[oo]));
            acc1[oo] = fmaf(s1.x, wv.x, fmaf(s1.y, wv.y, acc1[oo]));
        }
    }

    // warp reductions + scatter (lane 0 writes both tokens)
    #pragma unroll
    for (int oo = 0; oo < ONUM; oo++) {
        float v0 = acc0[oo], v1 = acc1[oo];
        #pragma unroll
        for (int off = 16; off; off >>= 1) {
            v0 += __shfl_down_sync(0xffffffffu, v0, off);
            v1 += __shfl_down_sync(0xffffffffu, v1, off);
        }
        if (lane == 0) {
            const int o = OBASE + oo;
            const int kblk = o / 9;
            const int l = o - kblk * 9;
            float* tbl = (kblk == 0) ? g_ps : (kblk == 1) ? g_pe : g_pa;
            tbl[t0 * PSTRIDE + l] = v0;
            tbl[(t0 + 1) * PSTRIDE + l] = v1;
        }
    }
}

__global__ __launch_bounds__(PROJ_TPB) void proj_kernel(const float* __restrict__ seq,
                                                        const float* __restrict__ W) {
    __shared__ float2 ws[ONUM * K2];    // 9 KB
    const int tg = blockIdx.x;
    switch (blockIdx.y) {
        case 0: proj_body<0>(seq, W, ws, tg); break;
        case 1: proj_body<3>(seq, W, ws, tg); break;
        case 2: proj_body<6>(seq, W, ws, tg); break;
        case 3: proj_body<9>(seq, W, ws, tg); break;
        case 4: proj_body<12>(seq, W, ws, tg); break;
        case 5: proj_body<15>(seq, W, ws, tg); break;
        case 6: proj_body<18>(seq, W, ws, tg); break;
        case 7: proj_body<21>(seq, W, ws, tg); break;
        default: proj_body<24>(seq, W, ws, tg); break;
    }
}

// ---------------------------------------------------------------------------
// Kernel B: single block, 576 threads.
//  (1) width-projection LUT + bias, (2) 1/w LUT,
//  (3) exclusive prefix-scan of g_pa: 18 warps = 9 labels x 2 half-sequences
//      (256 tokens each). Values preloaded as independent LDGs; halves joined
//      via smem totals + one barrier.
// ---------------------------------------------------------------------------
#define SCAN_TPB 576

__global__ __launch_bounds__(SCAN_TPB) void scan_kernel(const float* __restrict__ width_table,
                                                        const float* __restrict__ W,
                                                        const float* __restrict__ b) {
    __shared__ float tot[NUM_LABELS][2];
    const int tid = threadIdx.x;

    // pw[w][l] = b[l] + width_table[w] . W[l, 2304:2354]
    if (tid < (MAX_SPAN_LEN + 1) * NUM_LABELS) {
        const int w = tid / NUM_LABELS;
        const int l = tid - w * NUM_LABELS;
        const float* wrow = W + (size_t)l * W_COLS + 3 * EMBED_DIM;
        const float* wt = width_table + w * WIDTH_EMB;
        float acc = b[l];
        #pragma unroll
        for (int j = 0; j < WIDTH_EMB; j++)
            acc = fmaf(wt[j], wrow[j], acc);
        g_pw[w * PSTRIDE + l] = acc;
    }
    if (tid <= MAX_SPAN_LEN)
        g_invw[tid] = 1.0f / (float)(tid < 1 ? 1 : tid);

    const int warp = tid >> 5;
    const int lane = tid & 31;
    const int l = warp >> 1;        // label 0..8
    const int h = warp & 1;         // half 0..1
    const int tbase = h * 256;

    float v[8];
    float carry = 0.f;
    if (warp < 18) {
        // preload 8 values (independent LDGs)
        #pragma unroll
        for (int c = 0; c < 8; c++)
            v[c] = g_pa[(tbase + c * 32 + lane) * PSTRIDE + l];
        // local exclusive scan of the 256-token half; v[c] becomes excl value
        #pragma unroll
        for (int c = 0; c < 8; c++) {
            const float orig = v[c];
            float x = orig;
            #pragma unroll
            for (int off = 1; off < 32; off <<= 1) {
                float y = __shfl_up_sync(0xffffffffu, x, off);
                if (lane >= off) x += y;
            }
            v[c] = carry + x - orig;
            carry += __shfl_sync(0xffffffffu, x, 31);
        }
        if (lane == 0) tot[l][h] = carry;   // half total
    }
    __syncthreads();

    if (warp < 18) {
        const float offset = h ? tot[l][0] : 0.f;
        #pragma unroll
        for (int c = 0; c < 8; c++)
            g_pacs[(tbase + c * 32 + lane) * PSTRIDE + l] = v[c] + offset;
        // t = 512 entry: grand total
        if (h == 1 && lane == 0)
            g_pacs[SEQ_LEN * PSTRIDE + l] = tot[l][0] + tot[l][1];
    }
}

// ---------------------------------------------------------------------------
// Kernel C: one thread per span. All tables staged in dynamic smem (~82 KB),
// gathers become LDS; output staged through smem for coalesced float4 stores.
// ---------------------------------------------------------------------------
#define SPAN_BLK 256
// float4 counts
#define NPS4   (SEQ_LEN * 3)        // 1536
#define NPACS4 ((SEQ_LEN + 1) * 3)  // 1539
#define NPW4   ((MAX_SPAN_LEN + 1) * 3) // 51
#define SPAN_SMEM_FLOATS (NPS4 * 4 * 2 + NPACS4 * 4 + NPW4 * 4 + 20 + SPAN_BLK * NUM_LABELS)
#define SPAN_SMEM_BYTES (SPAN_SMEM_FLOATS * 4)

__global__ __launch_bounds__(SPAN_BLK) void span_kernel(const int* __restrict__ sidx,
                                                        const int* __restrict__ eidx,
                                                        const int* __restrict__ widx,
                                                        float* __restrict__ out) {
    extern __shared__ float smf[];
    float4* tps   = (float4*)smf;
    float4* tpe   = tps + NPS4;
    float4* tpacs = tpe + NPS4;
    float4* tpw   = tpacs + NPACS4;
    float*  sinv  = (float*)(tpw + NPW4);          // 17 floats (+3 pad)
    float*  so    = sinv + 20;                     // SPAN_BLK*9 floats

    const int tid = threadIdx.x;
    const int n = blockIdx.x * SPAN_BLK + tid;

    // span indices first: their L2 latency hides under the table fill
    const int s = sidx[n];
    const int e = eidx[n];
    const int w = widx[n];

    // cooperative fill of the tables
    const float4* gps   = (const float4*)g_ps;
    const float4* gpe   = (const float4*)g_pe;
    const float4* gpacs = (const float4*)g_pacs;
    const float4* gpw   = (const float4*)g_pw;
    #pragma unroll
    for (int i = tid; i < NPS4; i += SPAN_BLK) {
        tps[i] = gps[i];
        tpe[i] = gpe[i];
    }
    #pragma unroll
    for (int i = tid; i < NPACS4; i += SPAN_BLK)
        tpacs[i] = gpacs[i];
    if (tid < NPW4) tpw[tid] = gpw[tid];
    if (tid <= MAX_SPAN_LEN) sinv[tid] = g_invw[tid];
    __syncthreads();

    const float invw = sinv[w];
    const float4* ps = tps + s * 3;
    const float4* pe = tpe + e * 3;
    const float4* c0 = tpacs + s * 3;
    const float4* c1 = tpacs + e * 3;
    const float4* pw = tpw + w * 3;

    float r[12];
    #pragma unroll
    for (int q = 0; q < 3; q++) {
        const float4 a = ps[q], bb = pe[q], x0 = c0[q], x1 = c1[q], d = pw[q];
        r[q * 4 + 0] = a.x + bb.x + (x1.x - x0.x) * invw + d.x;
        r[q * 4 + 1] = a.y + bb.y + (x1.y - x0.y) * invw + d.y;
        r[q * 4 + 2] = a.z + bb.z + (x1.z - x0.z) * invw + d.z;
        r[q * 4 + 3] = a.w + bb.w + (x1.w - x0.w) * invw + d.w;
    }

    #pragma unroll
    for (int l = 0; l < NUM_LABELS; l++)
        so[tid * NUM_LABELS + l] = r[l];
    __syncthreads();

    float4* ob = (float4*)(out + (size_t)blockIdx.x * SPAN_BLK * NUM_LABELS);
    const float4* sb = (const float4*)so;
    #pragma unroll
    for (int i = tid; i < SPAN_BLK * NUM_LABELS / 4; i += SPAN_BLK)
        ob[i] = sb[i];
}

// ---------------------------------------------------------------------------
// Launcher
// ---------------------------------------------------------------------------
extern "C" void kernel_launch(void* const* d_in, const int* in_sizes, int n_in,
                              void* d_out, int out_size) {
    const float* seq   = (const float*)d_in[0];   // [1, 512, 768]
    const int*   sidx  = (const int*)d_in[1];     // [32768]
    const int*   eidx  = (const int*)d_in[2];     // [32768]
    const int*   widx  = (const int*)d_in[3];     // [32768]
    const float* wtab  = (const float*)d_in[4];   // [17, 50]
    const float* W     = (const float*)d_in[5];   // [9, 2354]
    const float* b     = (const float*)d_in[6];   // [9]
    float* out = (float*)d_out;                   // [32768, 9]

    cudaFuncSetAttribute(span_kernel, cudaFuncAttributeMaxDynamicSharedMemorySize,
                         SPAN_SMEM_BYTES);

    dim3 pgrid(SEQ_LEN / 16, 9);
    proj_kernel<<<pgrid, PROJ_TPB>>>(seq, W);
    scan_kernel<<<1, SCAN_TPB>>>(wtab, W, b);
    span_kernel<<<N_SPANS / SPAN_BLK, SPAN_BLK, SPAN_SMEM_BYTES>>>(sidx, eidx, widx, out);
}

// round 11
// speedup vs baseline: 1.6416x; 1.2882x over previous
#include <cuda_runtime.h>
#include <cuda_bf16.h>

// Problem constants
#define SEQ_LEN 512
#define EMBED_DIM 768
#define MAX_SPAN_LEN 16
#define WIDTH_EMB 50
#define NUM_LABELS 9
#define N_SPANS 32768
#define W_COLS (3 * EMBED_DIM + WIDTH_EMB)   // 2354

#define PSTRIDE 12            // padded table row: 9 floats in 12 -> 48B, 16B aligned
#define K2 (EMBED_DIM / 2)    // 384 float2 per 768-block row

#define NBLK 144              // <= SM count (148/152) -> all blocks resident
#define TPB 512

#define SPANS_PER_BLK 228     // 144 * 228 = 32832 >= 32768; multiple of 4

// Scratch tables (device globals; no allocation allowed)
__device__ float g_ps[SEQ_LEN * PSTRIDE];
__device__ float g_pe[SEQ_LEN * PSTRIDE];
__device__ float g_pa[SEQ_LEN * PSTRIDE];
__device__ float g_pacs[(SEQ_LEN + 8) * PSTRIDE];
__device__ float g_pw[(MAX_SPAN_LEN + 1) * PSTRIDE];
__device__ float g_invw[MAX_SPAN_LEN + 4];
__device__ unsigned long long g_bar;   // monotonic grid barrier (never reset)

// ---------------------------------------------------------------------------
// Grid-wide sync: all NBLK blocks resident by construction. Monotonic counter
// so graph replays need no reset: each barrier round consumes one full NBLK
// range; a block cannot reach round k+1 before round k fully completes.
// ---------------------------------------------------------------------------
__device__ __forceinline__ void grid_sync() {
    __syncthreads();
    if (threadIdx.x == 0) {
        __threadfence();                                   // release our writes
        unsigned long long old = atomicAdd(&g_bar, 1ULL);
        unsigned long long target = (old / NBLK + 1ULL) * (unsigned long long)NBLK;
        while (*(volatile unsigned long long*)&g_bar < target)
            __nanosleep(64);
        __threadfence();                                   // acquire others' writes
    }
    __syncthreads();
}

// Dynamic smem layout (union across phases):
//  Phase A: 2 x [3*K2] float2 tiles (one per 256-thread half)    = 18 KB
//  Phase C: tps[1536]f4 tpe[1536]f4 tpacs[1548]f4 tpw[64]f4,
//           sinv[32]f, so[2052]f                                  = ~83 KB
#define NPS4   1536
#define NPACS4 1539
#define SMEM_BYTES ((1536 + 1536 + 1548 + 64) * 16 + (32 + SPANS_PER_BLK * NUM_LABELS) * 4)

extern "C" __global__ void __launch_bounds__(TPB, 1)
fused_kernel(const float* __restrict__ seq,
             const int*   __restrict__ sidx,
             const int*   __restrict__ eidx,
             const int*   __restrict__ widx,
             const float* __restrict__ wtab,
             const float* __restrict__ W,
             const float* __restrict__ b,
             float* __restrict__ out) {
    extern __shared__ float smf[];
    const int tid = threadIdx.x;
    const int lane = tid & 31;

    // =========================== Phase A: proj ===========================
    {
        const int half = tid >> 8;                 // 0/1: two concurrent items
        const int tid256 = tid & 255;
        const int wl = tid256 >> 5;                // warp within half
        const int item = blockIdx.x * 2 + half;    // [0, 288)
        const int tg = item / 9;
        const int og = item - tg * 9;              // 3 outputs per item
        const int t0 = tg * 16 + wl * 2;

        float2* ws = ((float2*)smf) + half * (3 * K2);
        const float2* __restrict__ w2 = (const float2*)W;   // rows 8B-aligned
        const float2* __restrict__ s2a = (const float2*)(seq + (size_t)t0 * EMBED_DIM);
        const float2* __restrict__ s2b = (const float2*)(seq + (size_t)(t0 + 1) * EMBED_DIM);

        // prefetch both tokens' seq rows (24 independent coalesced LDG.64)
        float2 sv0[12], sv1[12];
        #pragma unroll
        for (int kk = 0; kk < 12; kk++) sv0[kk] = s2a[kk * 32 + lane];
        #pragma unroll
        for (int kk = 0; kk < 12; kk++) sv1[kk] = s2b[kk * 32 + lane];

        // cooperative fill of this half's 3 W rows (LDG latency overlaps above)
        #pragma unroll
        for (int i = tid256; i < 3 * K2; i += 256) {
            const int oo = i / K2;
            const int j2 = i - oo * K2;
            const int o = og * 3 + oo;
            const int kblk = (o >= 18) ? 2 : (o >= 9 ? 1 : 0);
            const int l = o - kblk * 9;
            ws[i] = __ldg(w2 + l * (W_COLS / 2) + kblk * (EMBED_DIM / 2) + j2);
        }
        __syncthreads();   // whole block: both halves execute identical count

        float acc0[3], acc1[3];
        #pragma unroll
        for (int o = 0; o < 3; o++) { acc0[o] = 0.f; acc1[o] = 0.f; }

        #pragma unroll
        for (int kk = 0; kk < 12; kk++) {
            const float2 s0 = sv0[kk];
            const float2 s1 = sv1[kk];
            #pragma unroll
            for (int oo = 0; oo < 3; oo++) {
                const float2 wv = ws[oo * K2 + kk * 32 + lane];
                acc0[oo] = fmaf(s0.x, wv.x, fmaf(s0.y, wv.y, acc0[oo]));
                acc1[oo] = fmaf(s1.x, wv.x, fmaf(s1.y, wv.y, acc1[oo]));
            }
        }

        #pragma unroll
        for (int oo = 0; oo < 3; oo++) {
            float v0 = acc0[oo], v1 = acc1[oo];
            #pragma unroll
            for (int off = 16; off; off >>= 1) {
                v0 += __shfl_down_sync(0xffffffffu, v0, off);
                v1 += __shfl_down_sync(0xffffffffu, v1, off);
            }
            if (lane == 0) {
                const int o = og * 3 + oo;
                const int kblk = (o >= 18) ? 2 : (o >= 9 ? 1 : 0);
                const int l = o - kblk * 9;
                float* tbl = (kblk == 0) ? g_ps : (kblk == 1) ? g_pe : g_pa;
                tbl[t0 * PSTRIDE + l] = v0;
                tbl[(t0 + 1) * PSTRIDE + l] = v1;
            }
        }
    }

    grid_sync();

    // ==================== Phase B: scan + pw LUT + invw ====================
    if (blockIdx.x < NUM_LABELS) {
        // exclusive prefix scan of g_pa[:, l] over 512 tokens, two-level
        const int l = blockIdx.x;
        __shared__ float ctot[16];
        __shared__ float coff[16];
        const int wl = tid >> 5;

        float v0 = 0.f, v1 = 0.f, x0 = 0.f, x1 = 0.f;
        if (tid < 256) {
            v0 = g_pa[tid * PSTRIDE + l];
            v1 = g_pa[(tid + 256) * PSTRIDE + l];
            x0 = v0; x1 = v1;
            #pragma unroll
            for (int off = 1; off < 32; off <<= 1) {
                float y0 = __shfl_up_sync(0xffffffffu, x0, off);
                float y1 = __shfl_up_sync(0xffffffffu, x1, off);
                if (lane >= off) { x0 += y0; x1 += y1; }
            }
            if (lane == 31) { ctot[wl] = x0; ctot[wl + 8] = x1; }
        }
        __syncthreads();
        if (tid < 32) {
            float tv = (tid < 16) ? ctot[tid] : 0.f;
            float xi = tv;
            #pragma unroll
            for (int off = 1; off < 32; off <<= 1) {
                float y = __shfl_up_sync(0xffffffffu, xi, off);
                if (lane >= off) xi += y;
            }
            if (tid < 16) coff[tid] = xi - tv;            // exclusive offsets
            if (tid == 15) g_pacs[SEQ_LEN * PSTRIDE + l] = xi;   // grand total
        }
        __syncthreads();
        if (tid < 256) {
            g_pacs[tid * PSTRIDE + l] = coff[wl] + x0 - v0;
            g_pacs[(tid + 256) * PSTRIDE + l] = coff[wl + 8] + x1 - v1;
        }
    } else if (blockIdx.x == NUM_LABELS) {
        // pw[w][l] = b[l] + width_table[w] . W[l, 2304:2354]; invw LUT
        if (tid < (MAX_SPAN_LEN + 1) * NUM_LABELS) {
            const int w = tid / NUM_LABELS;
            const int l = tid - w * NUM_LABELS;
            const float* wrow = W + (size_t)l * W_COLS + 3 * EMBED_DIM;
            const float* wt = wtab + w * WIDTH_EMB;
            float acc = b[l];
            #pragma unroll
            for (int j = 0; j < WIDTH_EMB; j++)
                acc = fmaf(wt[j], wrow[j], acc);
            g_pw[w * PSTRIDE + l] = acc;
        }
        if (tid <= MAX_SPAN_LEN)
            g_invw[tid] = 1.0f / (float)(tid < 1 ? 1 : tid);
    }

    grid_sync();

    // =========================== Phase C: spans ===========================
    {
        float4* tps   = (float4*)smf;
        float4* tpe   = tps + 1536;
        float4* tpacs = tpe + 1536;
        float4* tpw   = tpacs + 1548;
        float*  sinv  = (float*)(tpw + 64);
        float*  so    = sinv + 32;

        const int base = blockIdx.x * SPANS_PER_BLK;
        const int count = (N_SPANS - base < SPANS_PER_BLK) ? (N_SPANS - base)
                                                           : SPANS_PER_BLK;

        // span indices first: L2 latency hides under the table fill
        int s = 0, e = 0, w = 0;
        if (tid < count) {
            s = sidx[base + tid];
            e = eidx[base + tid];
            w = widx[base + tid];
        }

        const float4* gps   = (const float4*)g_ps;
        const float4* gpe   = (const float4*)g_pe;
        const float4* gpacs = (const float4*)g_pacs;
        const float4* gpw   = (const float4*)g_pw;
        #pragma unroll
        for (int i = tid; i < NPS4; i += TPB) {
            tps[i] = gps[i];
            tpe[i] = gpe[i];
        }
        #pragma unroll
        for (int i = tid; i < NPACS4; i += TPB)
            tpacs[i] = gpacs[i];
        if (tid < (MAX_SPAN_LEN + 1) * 3) tpw[tid] = gpw[tid];
        if (tid <= MAX_SPAN_LEN) sinv[tid] = g_invw[tid];
        __syncthreads();

        if (tid < count) {
            const float invw = sinv[w];
            const float4* ps = tps + s * 3;
            const float4* pe = tpe + e * 3;
            const float4* c0 = tpacs + s * 3;
            const float4* c1 = tpacs + e * 3;
            const float4* pw = tpw + w * 3;

            float r[12];
            #pragma unroll
            for (int q = 0; q < 3; q++) {
                const float4 a = ps[q], bb = pe[q], x0 = c0[q], x1 = c1[q], d = pw[q];
                r[q * 4 + 0] = a.x + bb.x + (x1.x - x0.x) * invw + d.x;
                r[q * 4 + 1] = a.y + bb.y + (x1.y - x0.y) * invw + d.y;
                r[q * 4 + 2] = a.z + bb.z + (x1.z - x0.z) * invw + d.z;
                r[q * 4 + 3] = a.w + bb.w + (x1.w - x0.w) * invw + d.w;
            }
            #pragma unroll
            for (int l = 0; l < NUM_LABELS; l++)
                so[tid * NUM_LABELS + l] = r[l];
        }
        __syncthreads();

        // coalesced float4 output copy (base*9 and count*9 divisible by 4)
        const int nf4 = count * NUM_LABELS / 4;
        float4* ob = (float4*)(out + (size_t)base * NUM_LABELS);
        const float4* sb = (const float4*)so;
        for (int i = tid; i < nf4; i += TPB)
            ob[i] = sb[i];
    }
}

// ---------------------------------------------------------------------------
// Launcher: one kernel, one launch.
// ---------------------------------------------------------------------------
extern "C" void kernel_launch(void* const* d_in, const int* in_sizes, int n_in,
                              void* d_out, int out_size) {
    const float* seq   = (const float*)d_in[0];   // [1, 512, 768]
    const int*   sidx  = (const int*)d_in[1];     // [32768]
    const int*   eidx  = (const int*)d_in[2];     // [32768]
    const int*   widx  = (const int*)d_in[3];     // [32768]
    const float* wtab  = (const float*)d_in[4];   // [17, 50]
    const float* W     = (const float*)d_in[5];   // [9, 2354]
    const float* b     = (const float*)d_in[6];   // [9]
    float* out = (float*)d_out;                   // [32768, 9]

    cudaFuncSetAttribute(fused_kernel, cudaFuncAttributeMaxDynamicSharedMemorySize,
                         SMEM_BYTES);
    fused_kernel<<<NBLK, TPB, SMEM_BYTES>>>(seq, sidx, eidx, widx, wtab, W, b, out);
}

// round 12
// speedup vs baseline: 1.6457x; 1.0025x over previous
#include <cuda_runtime.h>
#include <cuda_bf16.h>

// Problem constants
#define SEQ_LEN 512
#define EMBED_DIM 768
#define MAX_SPAN_LEN 16
#define WIDTH_EMB 50
#define NUM_LABELS 9
#define N_SPANS 32768
#define W_COLS (3 * EMBED_DIM + WIDTH_EMB)   // 2354

#define PSTRIDE 12            // padded table row: 9 floats in 12 -> 48B, 16B aligned
#define K2 (EMBED_DIM / 2)    // 384 float2 per 768-block row

#define NBLK 144              // <= SM count -> all blocks resident
#define TPB 512

#define SPANS_PER_BLK 228     // 143*228+164 = 32768; 228*9 and 164*9 divisible by 4

// Scratch tables crossing the grid barrier (device globals; no allocation)
__device__ float g_ps[SEQ_LEN * PSTRIDE];
__device__ float g_pe[SEQ_LEN * PSTRIDE];
__device__ float g_pa[SEQ_LEN * PSTRIDE];
__device__ unsigned long long g_bar;   // monotonic grid barrier (never reset)

// ---------------------------------------------------------------------------
// Grid-wide sync: all NBLK blocks resident by construction. Monotonic counter
// so graph replays need no reset.
// ---------------------------------------------------------------------------
__device__ __forceinline__ void grid_sync() {
    __syncthreads();
    if (threadIdx.x == 0) {
        __threadfence();                                   // release our writes
        unsigned long long old = atomicAdd(&g_bar, 1ULL);
        unsigned long long target = (old / NBLK + 1ULL) * (unsigned long long)NBLK;
        while (*(volatile unsigned long long*)&g_bar < target)
            __nanosleep(32);
        __threadfence();                                   // acquire others' writes
    }
    __syncthreads();
}

// Dynamic smem layout (union across phases):
//  Phase A: 2 x [3*K2] float2 tiles                                = 18 KB
//  Phase C: tps[1536]f4, tpe[1536]f4, tpacs[6160]f, tpw[208]f,
//           sinv[32]f, so[2052]f                                   = ~83 KB
#define NT4 1536                               // float4 per ps/pe/pa table
#define SMEM_FLOATS (NT4 * 4 * 2 + 6160 + 208 + 32 + SPANS_PER_BLK * NUM_LABELS)
#define SMEM_BYTES (SMEM_FLOATS * 4)

extern "C" __global__ void __launch_bounds__(TPB, 1)
fused_kernel(const float* __restrict__ seq,
             const int*   __restrict__ sidx,
             const int*   __restrict__ eidx,
             const int*   __restrict__ widx,
             const float* __restrict__ wtab,
             const float* __restrict__ W,
             const float* __restrict__ b,
             float* __restrict__ out) {
    extern __shared__ float smf[];
    const int tid = threadIdx.x;
    const int lane = tid & 31;
    const int warp = tid >> 5;

    // =========================== Phase A: proj ===========================
    // 288 (token-group x output-group) items, 2 per block (one per 256-half).
    {
        const int half = tid >> 8;
        const int tid256 = tid & 255;
        const int wl = tid256 >> 5;
        const int item = blockIdx.x * 2 + half;    // [0, 288)
        const int tg = item / 9;
        const int og = item - tg * 9;              // 3 outputs per item
        const int t0 = tg * 16 + wl * 2;

        float2* ws = ((float2*)smf) + half * (3 * K2);
        const float2* __restrict__ w2 = (const float2*)W;   // rows 8B-aligned
        const float2* __restrict__ s2a = (const float2*)(seq + (size_t)t0 * EMBED_DIM);
        const float2* __restrict__ s2b = (const float2*)(seq + (size_t)(t0 + 1) * EMBED_DIM);

        // prefetch both tokens' seq rows (24 independent coalesced LDG.64)
        float2 sv0[12], sv1[12];
        #pragma unroll
        for (int kk = 0; kk < 12; kk++) sv0[kk] = s2a[kk * 32 + lane];
        #pragma unroll
        for (int kk = 0; kk < 12; kk++) sv1[kk] = s2b[kk * 32 + lane];

        // cooperative fill of this half's 3 W rows (LDG latency overlaps above)
        #pragma unroll
        for (int i = tid256; i < 3 * K2; i += 256) {
            const int oo = i / K2;
            const int j2 = i - oo * K2;
            const int o = og * 3 + oo;
            const int kblk = (o >= 18) ? 2 : (o >= 9 ? 1 : 0);
            const int l = o - kblk * 9;
            ws[i] = __ldg(w2 + l * (W_COLS / 2) + kblk * (EMBED_DIM / 2) + j2);
        }
        __syncthreads();

        float acc0[3], acc1[3];
        #pragma unroll
        for (int o = 0; o < 3; o++) { acc0[o] = 0.f; acc1[o] = 0.f; }

        #pragma unroll
        for (int kk = 0; kk < 12; kk++) {
            const float2 s0 = sv0[kk];
            const float2 s1 = sv1[kk];
            #pragma unroll
            for (int oo = 0; oo < 3; oo++) {
                const float2 wv = ws[oo * K2 + kk * 32 + lane];
                acc0[oo] = fmaf(s0.x, wv.x, fmaf(s0.y, wv.y, acc0[oo]));
                acc1[oo] = fmaf(s1.x, wv.x, fmaf(s1.y, wv.y, acc1[oo]));
            }
        }

        #pragma unroll
        for (int oo = 0; oo < 3; oo++) {
            float v0 = acc0[oo], v1 = acc1[oo];
            #pragma unroll
            for (int off = 16; off; off >>= 1) {
                v0 += __shfl_down_sync(0xffffffffu, v0, off);
                v1 += __shfl_down_sync(0xffffffffu, v1, off);
            }
            if (lane == 0) {
                const int o = og * 3 + oo;
                const int kblk = (o >= 18) ? 2 : (o >= 9 ? 1 : 0);
                const int l = o - kblk * 9;
                float* tbl = (kblk == 0) ? g_ps : (kblk == 1) ? g_pe : g_pa;
                tbl[t0 * PSTRIDE + l] = v0;
                tbl[(t0 + 1) * PSTRIDE + l] = v1;
            }
        }
    }

    grid_sync();   // the ONLY grid-wide barrier

    // ============ Phase C: per-block scan + LUTs + span compute ============
    {
        float4* tps   = (float4*)smf;                  // [1536]
        float4* tpe   = tps + NT4;                     // [1536]
        float*  tpacs = (float*)(tpe + NT4);           // [6160] rows 0..512 x 12
        float*  tpw   = tpacs + 6160;                  // [208]  rows 0..16  x 12
        float*  sinv  = tpw + 208;                     // [32]
        float*  so    = sinv + 32;                     // [SPANS_PER_BLK*9]

        const int base = blockIdx.x * SPANS_PER_BLK;
        const int count = (N_SPANS - base < SPANS_PER_BLK) ? (N_SPANS - base)
                                                           : SPANS_PER_BLK;

        // span indices first: L2 latency hides under the table fill
        int s = 0, e = 0, w = 1;
        if (tid < count) {
            s = sidx[base + tid];
            e = eidx[base + tid];
            w = widx[base + tid];
        }

        // cooperative fill: ps, pe, and raw pa (into tpacs; scanned in place)
        const float4* gps = (const float4*)g_ps;
        const float4* gpe = (const float4*)g_pe;
        const float4* gpa = (const float4*)g_pa;
        float4* tpacs4 = (float4*)tpacs;
        #pragma unroll
        for (int i = tid; i < NT4; i += TPB) {
            tps[i] = gps[i];
            tpe[i] = gpe[i];
            tpacs4[i] = gpa[i];
        }
        __syncthreads();

        if (warp < NUM_LABELS) {
            // warp-per-label exclusive scan over 512 tokens, in place
            const int l = warp;
            float carry = 0.f;
            #pragma unroll 1
            for (int c = 0; c < 16; c++) {
                const int t = c * 32 + lane;
                const float v = tpacs[t * PSTRIDE + l];
                float x = v;
                #pragma unroll
                for (int off = 1; off < 32; off <<= 1) {
                    float y = __shfl_up_sync(0xffffffffu, x, off);
                    if (lane >= off) x += y;
                }
                tpacs[t * PSTRIDE + l] = carry + x - v;
                carry += __shfl_sync(0xffffffffu, x, 31);
            }
            if (lane == 0) tpacs[SEQ_LEN * PSTRIDE + l] = carry;   // grand total
        } else {
            // warps 9-15: pw LUT + invw (redundant per block, gmem reads L2-warm)
            const int ptid = tid - 288;                // 0..223
            if (ptid < (MAX_SPAN_LEN + 1) * NUM_LABELS) {
                const int ww = ptid / NUM_LABELS;
                const int l = ptid - ww * NUM_LABELS;
                const float* wrow = W + (size_t)l * W_COLS + 3 * EMBED_DIM;
                const float* wt = wtab + ww * WIDTH_EMB;
                float acc = b[l];
                #pragma unroll
                for (int j = 0; j < WIDTH_EMB; j++)
                    acc = fmaf(wt[j], wrow[j], acc);
                tpw[ww * PSTRIDE + l] = acc;
            }
            if (ptid >= 160 && ptid <= 160 + MAX_SPAN_LEN) {
                const int ww = ptid - 160;
                sinv[ww] = 1.0f / (float)(ww < 1 ? 1 : ww);
            }
        }
        __syncthreads();

        if (tid < count) {
            const float invw = sinv[w];
            const float4* ps = tps + s * 3;
            const float4* pe = tpe + e * 3;
            const float4* c0 = (const float4*)(tpacs + s * PSTRIDE);
            const float4* c1 = (const float4*)(tpacs + e * PSTRIDE);
            const float4* pw = (const float4*)(tpw + w * PSTRIDE);

            float r[12];
            #pragma unroll
            for (int q = 0; q < 3; q++) {
                const float4 a = ps[q], bb = pe[q], x0 = c0[q], x1 = c1[q], d = pw[q];
                r[q * 4 + 0] = a.x + bb.x + (x1.x - x0.x) * invw + d.x;
                r[q * 4 + 1] = a.y + bb.y + (x1.y - x0.y) * invw + d.y;
                r[q * 4 + 2] = a.z + bb.z + (x1.z - x0.z) * invw + d.z;
                r[q * 4 + 3] = a.w + bb.w + (x1.w - x0.w) * invw + d.w;
            }
            #pragma unroll
            for (int l = 0; l < NUM_LABELS; l++)
                so[tid * NUM_LABELS + l] = r[l];
        }
        __syncthreads();

        // coalesced float4 output copy
        const int nf4 = count * NUM_LABELS / 4;
        float4* ob = (float4*)(out + (size_t)base * NUM_LABELS);
        const float4* sb = (const float4*)so;
        for (int i = tid; i < nf4; i += TPB)
            ob[i] = sb[i];
    }
}

// ---------------------------------------------------------------------------
// Launcher: one kernel, one launch.
// ---------------------------------------------------------------------------
extern "C" void kernel_launch(void* const* d_in, const int* in_sizes, int n_in,
                              void* d_out, int out_size) {
    const float* seq   = (const float*)d_in[0];   // [1, 512, 768]
    const int*   sidx  = (const int*)d_in[1];     // [32768]
    const int*   eidx  = (const int*)d_in[2];     // [32768]
    const int*   widx  = (const int*)d_in[3];     // [32768]
    const float* wtab  = (const float*)d_in[4];   // [17, 50]
    const float* W     = (const float*)d_in[5];   // [9, 2354]
    const float* b     = (const float*)d_in[6];   // [9]
    float* out = (float*)d_out;                   // [32768, 9]

    cudaFuncSetAttribute(fused_kernel, cudaFuncAttributeMaxDynamicSharedMemorySize,
                         SMEM_BYTES);
    fused_kernel<<<NBLK, TPB, SMEM_BYTES>>>(seq, sidx, eidx, widx, wtab, W, b, out);
}